// round 7
// baseline (speedup 1.0000x reference)
#include <cuda_runtime.h>

// x: (B=8, ns=4, D=512, nc=64) fp32
// out: concat(map_hidden, map_mask), each (B, D, 4, 64, 65) fp32.
// For rel in 0..3, base=1<<rel:
//   out[b,d,rel,i,j] = max(x[b,rel,d, i .. i+k-1]) where k=(j-i)/base,
//   valid when i%base==0, (j-i)%base==0, i<j<64. Mask = 1.0 at hits.
//
// Pure store-bound (~545 MB out). Grid = (b,d) x rel x {hidden,mask}:
// mask CTAs are input-independent (no loads, no smem, no sync);
// hidden CTAs build a per-rel running-max table then gather.

#define B_DIM 8
#define D_DIM 512
#define NC 64
#define NJ 65
#define REGION (4 * NC * NJ)        // 16640 floats per half per (b,d)
#define RELBLK (NC * NJ)            // 4160 floats per rel block

// ---------- hidden-half worker: table build + gather ----------
template<int REL>
__device__ __forceinline__ void prop3d_hid(
    const float* __restrict__ xrow,     // x[b, REL, d, :]
    float* __restrict__ dst,            // out + bd*REGION + REL*RELBLK
    float* __restrict__ Sp,             // shared, (64>>REL)^2 words
    float* __restrict__ xsh,            // shared, 64 words
    int tid)
{
    constexpr int W  = NC >> REL;       // rows and row width
    constexpr int BM = (1 << REL) - 1;

    if (tid < NC) xsh[tid] = xrow[tid];
    __syncthreads();

    if (tid < W) {
        int i = tid << REL;
        int base_off = tid * W;
        int emax = (i + W < NC) ? (i + W) : NC;
        float m = xsh[i];
        Sp[base_off] = m;
        #pragma unroll 4
        for (int e = i + 1; e < emax; e++) {
            m = fmaxf(m, xsh[e]);
            Sp[base_off + (e - i)] = m;
        }
    }
    __syncthreads();

    for (int qq = tid; qq < RELBLK / 4; qq += 256) {
        int er = qq << 2;
        int i  = er / 65;               // const divisor -> mulhi
        int j  = er - i * 65;

        float4 hv4;
        float* hp = reinterpret_cast<float*>(&hv4);

        #pragma unroll
        for (int l = 0; l < 4; l++) {
            int jj = j + l;
            int ii = i;
            if (jj >= NJ) { jj -= NJ; ii += 1; }
            int diff = jj - ii;
            bool hit;
            if (REL == 0) hit = (diff > 0) & (jj < NC);
            else          hit = (diff > 0) & (jj < NC) & (((ii | diff) & BM) == 0);
            hp[l] = hit ? Sp[(ii >> REL) * W + (diff >> REL) - 1] : 0.0f;
        }
        *reinterpret_cast<float4*>(dst + er) = hv4;
    }
}

// ---------- mask-half worker: pure predicate, no loads ----------
template<int REL>
__device__ __forceinline__ void prop3d_msk(
    float* __restrict__ dst,            // out + half + bd*REGION + REL*RELBLK
    int tid)
{
    constexpr int BM = (1 << REL) - 1;

    for (int qq = tid; qq < RELBLK / 4; qq += 256) {
        int er = qq << 2;
        int i  = er / 65;
        int j  = er - i * 65;

        float4 mv4;
        float* mp = reinterpret_cast<float*>(&mv4);

        #pragma unroll
        for (int l = 0; l < 4; l++) {
            int jj = j + l;
            int ii = i;
            if (jj >= NJ) { jj -= NJ; ii += 1; }
            int diff = jj - ii;
            bool hit;
            if (REL == 0) hit = (diff > 0) & (jj < NC);
            else          hit = (diff > 0) & (jj < NC) & (((ii | diff) & BM) == 0);
            mp[l] = hit ? 1.0f : 0.0f;
        }
        *reinterpret_cast<float4*>(dst + er) = mv4;
    }
}

__global__ __launch_bounds__(256, 1)
void prop3d_kernel(const float* __restrict__ x, float* __restrict__ out,
                   long half_elems) {
    __shared__ float xsh[NC];
    __shared__ float Sp[4096];          // rel0 worst case: 64x64 (16 KB)

    const int bid  = blockIdx.x;
    const int rel  = bid & 3;
    const int hsel = (bid >> 2) & 1;    // 0 = hidden, 1 = mask
    const int bd   = bid >> 3;          // b*512 + d
    const int b    = bd >> 9;
    const int d    = bd & 511;
    const int tid  = threadIdx.x;

    if (hsel == 0) {
        const float* xrow = x + ((((long)(b << 2) + rel) * D_DIM) + d) * NC;
        float* dst = out + (long)bd * REGION + rel * RELBLK;
        switch (rel) {
            case 0:  prop3d_hid<0>(xrow, dst, Sp, xsh, tid); break;
            case 1:  prop3d_hid<1>(xrow, dst, Sp, xsh, tid); break;
            case 2:  prop3d_hid<2>(xrow, dst, Sp, xsh, tid); break;
            default: prop3d_hid<3>(xrow, dst, Sp, xsh, tid); break;
        }
    } else {
        float* dst = out + half_elems + (long)bd * REGION + rel * RELBLK;
        switch (rel) {
            case 0:  prop3d_msk<0>(dst, tid); break;
            case 1:  prop3d_msk<1>(dst, tid); break;
            case 2:  prop3d_msk<2>(dst, tid); break;
            default: prop3d_msk<3>(dst, tid); break;
        }
    }
}

extern "C" void kernel_launch(void* const* d_in, const int* in_sizes, int n_in,
                              void* d_out, int out_size) {
    const float* x = (const float*)d_in[0];
    float* out = (float*)d_out;
    long half = (long)out_size / 2;     // map_hidden elements; map_mask follows

    prop3d_kernel<<<B_DIM * D_DIM * 4 * 2, 256>>>(x, out, half);
}